// round 1
// baseline (speedup 1.0000x reference)
#include <cuda_runtime.h>
#include <math.h>

// Fixed problem shape (KarrasOptimalDenoiser): B=64, D=3072, N=50000.
#define BMAX 64
#define NMAX 50000
#define DFIX 3072

// Scratch (allocation-free: __device__ globals).
__device__ float g_logits[(size_t)BMAX * NMAX];
__device__ float g_x2[BMAX];
__device__ float g_inv[BMAX];
__device__ float g_m[BMAX];
__device__ float g_is[BMAX];

// ---------------------------------------------------------------------------
// K0: per-b ||x_b||^2 and 1/sigma^2
// ---------------------------------------------------------------------------
__global__ void k_prep(const float* __restrict__ x,
                       const float* __restrict__ sigma, int D) {
    int b = blockIdx.x;
    const float* xr = x + (size_t)b * D;
    float s = 0.f;
    for (int d = threadIdx.x; d < D; d += blockDim.x) {
        float v = xr[d];
        s += v * v;
    }
    __shared__ float red[256];
    red[threadIdx.x] = s;
    __syncthreads();
    for (int o = 128; o > 0; o >>= 1) {
        if (threadIdx.x < o) red[threadIdx.x] += red[threadIdx.x + o];
        __syncthreads();
    }
    if (threadIdx.x == 0) {
        g_x2[b] = red[0];
        float sg = sigma[b];
        g_inv[b] = 1.0f / (sg * sg);
    }
}

// ---------------------------------------------------------------------------
// K1: logits[b][n] = -0.5 * max(||x_b||^2 + ||Y_n||^2 - 2 x_b.Y_n, 0) / sig^2
// SIMT fp32 GEMM, 64(b) x 64(n) tile per CTA, K streamed in tiles of 16.
// ||Y_n||^2 computed on the fly from the streamed tiles.
// ---------------------------------------------------------------------------
#define KT 16
#define NT 64

__global__ void __launch_bounds__(256, 2)
k_logits(const float* __restrict__ x, const float* __restrict__ Y,
         int N, int D) {
    __shared__ float As[KT][65];   // x tile, k-major, padded (conflict-free)
    __shared__ float Bs[KT][65];   // Y tile, k-major, padded
    __shared__ float y2s[NT];
    __shared__ float red[256];

    int t  = threadIdx.x;
    int n0 = blockIdx.x * NT;
    int lrow = t >> 2;             // 0..63 : row for global loads
    int lq   = t & 3;              // 0..3  : float4 slot within 16-wide k tile
    int tx = t & 15;               // n-dim micro-tile
    int ty = t >> 4;               // b-dim micro-tile

    float acc[4][4];
#pragma unroll
    for (int i = 0; i < 4; i++)
#pragma unroll
        for (int j = 0; j < 4; j++) acc[i][j] = 0.f;
    float y2p = 0.f;

    const float* xrow = x + (size_t)lrow * D + lq * 4;
    int nrow = n0 + lrow;
    bool bv = (nrow < N);
    const float* yrow = Y + (size_t)(bv ? nrow : 0) * D + lq * 4;

    for (int k0 = 0; k0 < D; k0 += KT) {
        float4 a = *(const float4*)(xrow + k0);
        float4 w = make_float4(0.f, 0.f, 0.f, 0.f);
        if (bv) w = *(const float4*)(yrow + k0);
        y2p += w.x * w.x + w.y * w.y + w.z * w.z + w.w * w.w;

        As[lq * 4 + 0][lrow] = a.x;
        As[lq * 4 + 1][lrow] = a.y;
        As[lq * 4 + 2][lrow] = a.z;
        As[lq * 4 + 3][lrow] = a.w;
        Bs[lq * 4 + 0][lrow] = w.x;
        Bs[lq * 4 + 1][lrow] = w.y;
        Bs[lq * 4 + 2][lrow] = w.z;
        Bs[lq * 4 + 3][lrow] = w.w;
        __syncthreads();

#pragma unroll
        for (int kk = 0; kk < KT; kk++) {
            float av[4], bw[4];
#pragma unroll
            for (int i = 0; i < 4; i++) av[i] = As[kk][ty * 4 + i];
#pragma unroll
            for (int j = 0; j < 4; j++) bw[j] = Bs[kk][tx * 4 + j];
#pragma unroll
            for (int i = 0; i < 4; i++)
#pragma unroll
                for (int j = 0; j < 4; j++)
                    acc[i][j] = fmaf(av[i], bw[j], acc[i][j]);
        }
        __syncthreads();
    }

    // reduce partial ||Y_n||^2 across the 4 lq slots
    red[t] = y2p;
    __syncthreads();
    if (lq == 0) y2s[lrow] = red[t] + red[t + 1] + red[t + 2] + red[t + 3];
    __syncthreads();

    // epilogue: form logits
#pragma unroll
    for (int i = 0; i < 4; i++) {
        int b = ty * 4 + i;
        float x2b = g_x2[b];
        float iv  = g_inv[b];
#pragma unroll
        for (int j = 0; j < 4; j++) {
            int n = n0 + tx * 4 + j;
            if (n < N) {
                float d2 = x2b + y2s[tx * 4 + j] - 2.0f * acc[i][j];
                d2 = fmaxf(d2, 0.0f);
                g_logits[(size_t)b * N + n] = -0.5f * d2 * iv;
            }
        }
    }
}

// ---------------------------------------------------------------------------
// K2: per-b row max and 1/sum(exp(l - max))
// ---------------------------------------------------------------------------
__global__ void k_stats(int N) {
    int b = blockIdx.x, t = threadIdx.x;
    const float* row = g_logits + (size_t)b * N;
    __shared__ float red[256];

    float mx = -3.4e38f;
    for (int i = t; i < N; i += 256) mx = fmaxf(mx, row[i]);
    red[t] = mx;
    __syncthreads();
    for (int o = 128; o > 0; o >>= 1) {
        if (t < o) red[t] = fmaxf(red[t], red[t + o]);
        __syncthreads();
    }
    float M = red[0];
    __syncthreads();

    float s = 0.f;
    for (int i = t; i < N; i += 256) s += expf(row[i] - M);
    red[t] = s;
    __syncthreads();
    for (int o = 128; o > 0; o >>= 1) {
        if (t < o) red[t] += red[t + o];
        __syncthreads();
    }
    if (t == 0) {
        g_m[b] = M;
        g_is[b] = 1.0f / red[0];
    }
}

// ---------------------------------------------------------------------------
// K3: out[b] = sum_n w[b,n] * Y[n], exploiting softmax sparsity.
// w < 1e-12 is skipped: neglected mass <= N*1e-12 = 5e-8 (<< 1e-3 tol).
// One CTA per b; accumulators live in registers (12 per thread).
// ---------------------------------------------------------------------------
#define CHUNK 2048
#define DREG (DFIX / 256)   // 12

__global__ void __launch_bounds__(256)
k_out(const float* __restrict__ Y, float* __restrict__ out, int N, int D) {
    int b = blockIdx.x, t = threadIdx.x;
    __shared__ int   lidx[CHUNK];
    __shared__ float lw[CHUNK];
    __shared__ int   cnt;

    float racc[DREG];
#pragma unroll
    for (int i = 0; i < DREG; i++) racc[i] = 0.f;
    if (t == 0) cnt = 0;

    float M  = g_m[b];
    float IS = g_is[b];
    const float* row = g_logits + (size_t)b * N;

    for (int c0 = 0; c0 < N; c0 += CHUNK) {
        __syncthreads();
#pragma unroll
        for (int j = 0; j < CHUNK / 256; j++) {
            int n = c0 + j * 256 + t;
            if (n < N) {
                float w = expf(row[n] - M) * IS;
                if (w > 1e-12f) {
                    int p = atomicAdd(&cnt, 1);
                    lidx[p] = n;
                    lw[p] = w;
                }
            }
        }
        __syncthreads();
        int c = cnt;
        for (int e = 0; e < c; e++) {
            int n = lidx[e];
            float w = lw[e];
            const float* yr = Y + (size_t)n * D + t;
#pragma unroll
            for (int i = 0; i < DREG; i++)
                racc[i] = fmaf(w, yr[i * 256], racc[i]);
        }
        __syncthreads();
        if (t == 0) cnt = 0;
    }
    __syncthreads();
#pragma unroll
    for (int i = 0; i < DREG; i++)
        out[(size_t)b * D + t + i * 256] = racc[i];
}

// ---------------------------------------------------------------------------
extern "C" void kernel_launch(void* const* d_in, const int* in_sizes, int n_in,
                              void* d_out, int out_size) {
    const float* x     = (const float*)d_in[0];  // [B, C, H, W] -> [B, D]
    const float* sigma = (const float*)d_in[1];  // [B]
    const float* Y     = (const float*)d_in[2];  // [N, C, H, W] -> [N, D]
    float* out = (float*)d_out;

    int B = in_sizes[1];               // 64
    int D = in_sizes[0] / B;           // 3072
    int N = in_sizes[2] / D;           // 50000

    k_prep<<<B, 256>>>(x, sigma, D);
    k_logits<<<(N + NT - 1) / NT, 256>>>(x, Y, N, D);
    k_stats<<<B, 256>>>(N);
    k_out<<<B, 256>>>(Y, out, N, D);
}

// round 3
// speedup vs baseline: 2.5341x; 2.5341x over previous
#include <cuda_runtime.h>
#include <cuda_bf16.h>
#include <math.h>
#include <stdint.h>

// Fixed problem shape: B=64, D=3072, N=50000.
#define BFIX 64
#define DFIX 3072
#define NFIX 50000

// ---------------- scratch (__device__ globals: allocation-free) -------------
__device__ float g_logits[(size_t)BFIX * NFIX];
__device__ float g_x2[BFIX];
__device__ float g_inv[BFIX];
__device__ float g_m[BFIX];
__device__ float g_is[BFIX];
__device__ __nv_bfloat16 g_xhi[BFIX * DFIX];
__device__ __nv_bfloat16 g_xlo[BFIX * DFIX];
__device__ float g_pm[BFIX * 32];
__device__ float g_ps[BFIX * 32];

// ---------------- helpers ----------------------------------------------------
__device__ __forceinline__ uint32_t smem_u32(const void* p) {
    uint32_t a;
    asm("{ .reg .u64 t; cvta.to.shared.u64 t, %1; cvt.u32.u64 %0, t; }"
        : "=r"(a) : "l"(p));
    return a;
}
#define SMEM_SWZ(o) ((o) ^ (((o) >> 3) & 0x70))

#define LDSM_X4(r, addr) \
    asm volatile("ldmatrix.sync.aligned.m8n8.x4.shared.b16 {%0,%1,%2,%3}, [%4];" \
        : "=r"((r)[0]), "=r"((r)[1]), "=r"((r)[2]), "=r"((r)[3]) : "r"(addr))

#define MMA16816(d, a, b0, b1) \
    asm volatile("mma.sync.aligned.m16n8k16.row.col.f32.bf16.bf16.f32 " \
        "{%0,%1,%2,%3}, {%4,%5,%6,%7}, {%8,%9}, {%0,%1,%2,%3};" \
        : "+f"((d)[0]), "+f"((d)[1]), "+f"((d)[2]), "+f"((d)[3]) \
        : "r"((a)[0]), "r"((a)[1]), "r"((a)[2]), "r"((a)[3]), "r"(b0), "r"(b1))

__device__ __forceinline__ uint32_t packbf2(__nv_bfloat16 a, __nv_bfloat16 b) {
    __nv_bfloat162 h = __halves2bfloat162(a, b);
    return *reinterpret_cast<uint32_t*>(&h);
}

// ---------------------------------------------------------------------------
// K0: x2, 1/sigma^2, and bf16 hi/lo split of x
// ---------------------------------------------------------------------------
__global__ void k_prep(const float* __restrict__ x,
                       const float* __restrict__ sigma, int D) {
    int b = blockIdx.x;
    const float* xr = x + (size_t)b * D;
    float s = 0.f;
    for (int d = threadIdx.x; d < D; d += blockDim.x) {
        float v = xr[d];
        s += v * v;
        __nv_bfloat16 hi = __float2bfloat16(v);
        float lof = v - __bfloat162float(hi);
        g_xhi[(size_t)b * D + d] = hi;
        g_xlo[(size_t)b * D + d] = __float2bfloat16(lof);
    }
    __shared__ float red[256];
    red[threadIdx.x] = s;
    __syncthreads();
    for (int o = 128; o > 0; o >>= 1) {
        if (threadIdx.x < o) red[threadIdx.x] += red[threadIdx.x + o];
        __syncthreads();
    }
    if (threadIdx.x == 0) {
        g_x2[b] = red[0];
        float sg = sigma[b];
        g_inv[b] = 1.0f / (sg * sg);
    }
}

// ---------------------------------------------------------------------------
// K1: HMMA (mma.sync bf16) split GEMM.  CTA tile M=64 x N=128, KC=64.
// dot = xhi.yhi + xhi.ylo + xlo.yhi, fp32 accum in registers.
// Y converted fp32->bf16 hi/lo on the fly; y2 fused.
// ---------------------------------------------------------------------------
#define NT 128
#define KC 64
#define TILE_A_LO 8192
#define TILE_B_HI 16384
#define TILE_B_LO 32768
#define BUF_SZ    49152
#define SOFF_RED  0
#define SOFF_Y2   1024
#define SMEM_PRE  2048
#define SMEM_TOTAL (SMEM_PRE + 1024 + 2 * BUF_SZ)

__global__ void __launch_bounds__(256)
k_gemm(const float* __restrict__ Y, int N, int D) {
    extern __shared__ char smem[];
    uint32_t sb = smem_u32(smem);
    const int t = threadIdx.x, w = t >> 5, lane = t & 31;
    const int n0 = blockIdx.x * NT;

    uint32_t tile0 = (sb + SMEM_PRE + 1023) & ~1023u;
    char* sm_t = smem + (tile0 - sb);
    float* redp = (float*)(smem + SOFF_RED);
    float* y2s  = (float*)(smem + SOFF_Y2);

    const int wm = w & 1;        // 0..1 : M 32-row half
    const int wn = w >> 1;       // 0..3 : N 32-col quarter

    // loader mapping: Y row r (0..127), 32-float half ch; A row ar, 16-elem grp ap
    const int r  = t >> 1;
    const int ch = (t & 1) * 32;
    int gr = n0 + r; if (gr >= N) gr = N - 1;
    const float* yp = Y + (size_t)gr * D + ch;
    const int ar = t >> 2, ap = t & 3;
    const __nv_bfloat16* xhp = g_xhi + (size_t)ar * D + ap * 16;
    const __nv_bfloat16* xlp = g_xlo + (size_t)ar * D + ap * 16;

    // ldmatrix lane addressing
    const int rowA = wm * 32 + (lane & 15);
    const int rowB = wn * 32 + (lane & 15);
    const uint32_t kbl = (uint32_t)(lane >> 4) * 16;

    float acc[2][4][4];
#pragma unroll
    for (int i = 0; i < 2; i++)
#pragma unroll
        for (int j = 0; j < 4; j++)
#pragma unroll
            for (int k = 0; k < 4; k++) acc[i][j][k] = 0.f;

    float y2p = 0.f;
    float4 yv[8];
    uint4 ahv[2], alv[2];

    const int NC = D / KC;   // 48

    // ---- prologue: load + store chunk 0
#pragma unroll
    for (int j = 0; j < 8; j++) yv[j] = *(const float4*)(yp + j * 4);
    ahv[0] = *(const uint4*)(xhp); ahv[1] = *(const uint4*)(xhp + 8);
    alv[0] = *(const uint4*)(xlp); alv[1] = *(const uint4*)(xlp + 8);

#pragma unroll 1
    for (int ci = 0; ci < NC; ci++) {
        int buf = ci & 1;
        // store regs (chunk ci) into buf
        {
            char* base = sm_t + buf * BUF_SZ;
            char* bh = base + TILE_B_HI;
            char* bl = base + TILE_B_LO;
#pragma unroll
            for (int j = 0; j < 8; j++) {
                float4 v = yv[j];
                y2p += v.x * v.x + v.y * v.y + v.z * v.z + v.w * v.w;
                __nv_bfloat16 hx = __float2bfloat16(v.x), hy = __float2bfloat16(v.y);
                __nv_bfloat16 hz = __float2bfloat16(v.z), hw = __float2bfloat16(v.w);
                uint2 hu, lu;
                hu.x = packbf2(hx, hy); hu.y = packbf2(hz, hw);
                lu.x = packbf2(__float2bfloat16(v.x - __bfloat162float(hx)),
                               __float2bfloat16(v.y - __bfloat162float(hy)));
                lu.y = packbf2(__float2bfloat16(v.z - __bfloat162float(hz)),
                               __float2bfloat16(v.w - __bfloat162float(hw)));
                uint32_t bo = SMEM_SWZ((uint32_t)(r * 128 + (ch + j * 4) * 2));
                *(uint2*)(bh + bo) = hu;
                *(uint2*)(bl + bo) = lu;
            }
            char* aH = base;
            char* aL = base + TILE_A_LO;
#pragma unroll
            for (int u = 0; u < 2; u++) {
                uint32_t bo = SMEM_SWZ((uint32_t)(ar * 128 + ap * 32 + u * 16));
                *(uint4*)(aH + bo) = ahv[u];
                *(uint4*)(aL + bo) = alv[u];
            }
        }
        __syncthreads();

        // prefetch next chunk into regs (overlaps with MMA below)
        if (ci + 1 < NC) {
            int k0 = (ci + 1) * KC;
#pragma unroll
            for (int j = 0; j < 8; j++) yv[j] = *(const float4*)(yp + k0 + j * 4);
            ahv[0] = *(const uint4*)(xhp + k0); ahv[1] = *(const uint4*)(xhp + k0 + 8);
            alv[0] = *(const uint4*)(xlp + k0); alv[1] = *(const uint4*)(xlp + k0 + 8);
        }

        // MMA over buf
        {
            uint32_t base = tile0 + buf * BUF_SZ;
#pragma unroll
            for (int ks = 0; ks < 4; ks++) {
                uint32_t kb = (uint32_t)ks * 32 + kbl;
                uint32_t offA0 = SMEM_SWZ((uint32_t)(rowA * 128) + kb);
                uint32_t offA1 = SMEM_SWZ((uint32_t)((rowA + 16) * 128) + kb);
                uint32_t offB0 = SMEM_SWZ((uint32_t)(rowB * 128) + kb);
                uint32_t offB1 = SMEM_SWZ((uint32_t)((rowB + 16) * 128) + kb);
                uint32_t ah0[4], ah1[4], al0[4], al1[4];
                uint32_t bh0[4], bh1[4], bl0[4], bl1[4];
                LDSM_X4(ah0, base + offA0);
                LDSM_X4(ah1, base + offA1);
                LDSM_X4(al0, base + TILE_A_LO + offA0);
                LDSM_X4(al1, base + TILE_A_LO + offA1);
                LDSM_X4(bh0, base + TILE_B_HI + offB0);
                LDSM_X4(bh1, base + TILE_B_HI + offB1);
                LDSM_X4(bl0, base + TILE_B_LO + offB0);
                LDSM_X4(bl1, base + TILE_B_LO + offB1);
#pragma unroll
                for (int nt = 0; nt < 4; nt++) {
                    uint32_t* BH = (nt < 2) ? bh0 : bh1;
                    uint32_t* BL = (nt < 2) ? bl0 : bl1;
                    int p = nt & 1;
                    uint32_t b0h = BH[p], b1h = BH[2 + p];
                    uint32_t b0l = BL[p], b1l = BL[2 + p];
                    MMA16816(acc[0][nt], ah0, b0h, b1h);
                    MMA16816(acc[1][nt], ah1, b0h, b1h);
                    MMA16816(acc[0][nt], ah0, b0l, b1l);
                    MMA16816(acc[1][nt], ah1, b0l, b1l);
                    MMA16816(acc[0][nt], al0, b0h, b1h);
                    MMA16816(acc[1][nt], al1, b0h, b1h);
                }
            }
        }
        // next iteration stores into buf^1 (read during MMA two iters ago) -> safe
        if (ci + 1 < NC) __syncthreads();
    }

    // ---- epilogue: stage dots in SMEM (reuse buf0 region: 64x128 f32 = 32KB)
    float* lt = (float*)sm_t;
    __syncthreads();    // all MMA (last chunk used buf1) done; buf0 free
#pragma unroll
    for (int mt = 0; mt < 2; mt++) {
#pragma unroll
        for (int nt = 0; nt < 4; nt++) {
            int mrow = wm * 32 + mt * 16 + (lane >> 2);
            int col  = wn * 32 + nt * 8 + (lane & 3) * 2;
            lt[mrow * 128 + col]           = acc[mt][nt][0];
            lt[mrow * 128 + col + 1]       = acc[mt][nt][1];
            lt[(mrow + 8) * 128 + col]     = acc[mt][nt][2];
            lt[(mrow + 8) * 128 + col + 1] = acc[mt][nt][3];
        }
    }
    redp[t] = y2p;
    __syncthreads();
    if (t < 128) y2s[t] = redp[2 * t] + redp[2 * t + 1];
    __syncthreads();

#pragma unroll
    for (int it = 0; it < 8; it++) {
        int b = it * 8 + w;
        int nn = lane * 4;
        int n = n0 + nn;
        if (n < N) {
            float4 dv = *(float4*)(lt + b * 128 + nn);
            float x2b = g_x2[b];
            float iv  = g_inv[b];
            float4 o;
            o.x = -0.5f * fmaxf(x2b + y2s[nn]     - 2.0f * dv.x, 0.0f) * iv;
            o.y = -0.5f * fmaxf(x2b + y2s[nn + 1] - 2.0f * dv.y, 0.0f) * iv;
            o.z = -0.5f * fmaxf(x2b + y2s[nn + 2] - 2.0f * dv.z, 0.0f) * iv;
            o.w = -0.5f * fmaxf(x2b + y2s[nn + 3] - 2.0f * dv.w, 0.0f) * iv;
            *(float4*)(g_logits + (size_t)b * N + n) = o;
        }
    }
}

// ---------------------------------------------------------------------------
// K2a: per-(b, slice) partial max + sumexp.  grid (B, 32), 128 threads
// ---------------------------------------------------------------------------
__global__ void k_stats_part(int N) {
    int b = blockIdx.x, s = blockIdx.y, t = threadIdx.x;
    int L = (N + 31) / 32;
    int st = s * L, en = min(N, st + L);
    const float* row = g_logits + (size_t)b * N;
    __shared__ float red[128];

    float mx = -3.4e38f;
    for (int i = st + t; i < en; i += 128) mx = fmaxf(mx, row[i]);
    red[t] = mx;
    __syncthreads();
    for (int o = 64; o > 0; o >>= 1) {
        if (t < o) red[t] = fmaxf(red[t], red[t + o]);
        __syncthreads();
    }
    float M = red[0];
    __syncthreads();
    float sv = 0.f;
    for (int i = st + t; i < en; i += 128) sv += expf(row[i] - M);
    red[t] = sv;
    __syncthreads();
    for (int o = 64; o > 0; o >>= 1) {
        if (t < o) red[t] += red[t + o];
        __syncthreads();
    }
    if (t == 0) { g_pm[b * 32 + s] = M; g_ps[b * 32 + s] = red[0]; }
}

// K2b: merge 32 partials per b (one warp per b)
__global__ void k_stats_comb() {
    int b = blockIdx.x, t = threadIdx.x;
    float m = g_pm[b * 32 + t];
    float sp = g_ps[b * 32 + t];
    float M = m;
#pragma unroll
    for (int o = 16; o > 0; o >>= 1) M = fmaxf(M, __shfl_xor_sync(0xffffffff, M, o));
    float sv = sp * expf(m - M);
#pragma unroll
    for (int o = 16; o > 0; o >>= 1) sv += __shfl_xor_sync(0xffffffff, sv, o);
    if (t == 0) { g_m[b] = M; g_is[b] = 1.0f / sv; }
}

// ---------------------------------------------------------------------------
// K3: zero out, then sparse weighted gather with slice parallelism.
// ---------------------------------------------------------------------------
__global__ void k_zero(float* out, int n) {
    int i = blockIdx.x * blockDim.x + threadIdx.x;
    if (i < n) out[i] = 0.f;
}

#define OCHUNK 1024
#define DREG (DFIX / 256)

__global__ void __launch_bounds__(256)
k_out(const float* __restrict__ Y, float* __restrict__ out, int N, int D) {
    int b = blockIdx.x, s = blockIdx.y, t = threadIdx.x;
    int L = (N + 15) / 16;
    int st = s * L, en = min(N, st + L);
    __shared__ int lidx[OCHUNK];
    __shared__ float lw[OCHUNK];
    __shared__ int cnt;

    float racc[DREG];
#pragma unroll
    for (int i = 0; i < DREG; i++) racc[i] = 0.f;
    if (t == 0) cnt = 0;

    float M  = g_m[b];
    float IS = g_is[b];
    const float* row = g_logits + (size_t)b * N;
    int tot = 0;

    for (int c0 = st; c0 < en; c0 += OCHUNK) {
        __syncthreads();
#pragma unroll
        for (int j = 0; j < OCHUNK / 256; j++) {
            int n = c0 + j * 256 + t;
            if (n < en) {
                float wv = expf(row[n] - M) * IS;
                if (wv > 1e-12f) {
                    int p = atomicAdd(&cnt, 1);
                    lidx[p] = n;
                    lw[p] = wv;
                }
            }
        }
        __syncthreads();
        int c = cnt;
        tot += c;
        for (int e = 0; e < c; e++) {
            int n = lidx[e];
            float wv = lw[e];
            const float* yr = Y + (size_t)n * D + t;
#pragma unroll
            for (int i = 0; i < DREG; i++)
                racc[i] = fmaf(wv, yr[i * 256], racc[i]);
        }
        __syncthreads();
        if (t == 0) cnt = 0;
    }
    if (tot > 0) {
#pragma unroll
        for (int i = 0; i < DREG; i++)
            atomicAdd(&out[(size_t)b * D + t + i * 256], racc[i]);
    }
}

// ---------------------------------------------------------------------------
extern "C" void kernel_launch(void* const* d_in, const int* in_sizes, int n_in,
                              void* d_out, int out_size) {
    const float* x     = (const float*)d_in[0];
    const float* sigma = (const float*)d_in[1];
    const float* Y     = (const float*)d_in[2];
    float* out = (float*)d_out;

    int B = in_sizes[1];             // 64
    int D = in_sizes[0] / B;         // 3072
    int N = in_sizes[2] / D;         // 50000

    cudaFuncSetAttribute(k_gemm, cudaFuncAttributeMaxDynamicSharedMemorySize, SMEM_TOTAL);

    k_prep<<<B, 256>>>(x, sigma, D);
    k_gemm<<<(N + NT - 1) / NT, 256, SMEM_TOTAL>>>(Y, N, D);
    dim3 gs(B, 32);
    k_stats_part<<<gs, 128>>>(N);
    k_stats_comb<<<B, 32>>>();
    k_zero<<<(B * D + 255) / 256, 256>>>(out, B * D);
    dim3 go(B, 16);
    k_out<<<go, 256>>>(Y, out, N, D);
}

// round 4
// speedup vs baseline: 2.7507x; 1.0855x over previous
#include <cuda_runtime.h>
#include <cuda_bf16.h>
#include <math.h>
#include <stdint.h>

// Fixed problem shape: B=64, D=3072, N=50000.
#define BFIX 64
#define DFIX 3072

// ---------------- scratch (__device__ globals: allocation-free) -------------
__device__ float g_logits[(size_t)BFIX * 50048];
__device__ float g_x2[BFIX];
__device__ float g_inv[BFIX];
__device__ float g_m[BFIX];
__device__ float g_is[BFIX];
__device__ __nv_bfloat16 g_xhi[BFIX * DFIX];
__device__ __nv_bfloat16 g_xlo[BFIX * DFIX];
__device__ float g_pm[BFIX * 512];
__device__ float g_ps[BFIX * 512];

// ---------------- helpers ----------------------------------------------------
__device__ __forceinline__ uint32_t smem_u32(const void* p) {
    uint32_t a;
    asm("{ .reg .u64 t; cvta.to.shared.u64 t, %1; cvt.u32.u64 %0, t; }"
        : "=r"(a) : "l"(p));
    return a;
}
#define SMEM_SWZ(o) ((o) ^ (((o) >> 3) & 0x70))

#define LDSM_X4(r, addr) \
    asm volatile("ldmatrix.sync.aligned.m8n8.x4.shared.b16 {%0,%1,%2,%3}, [%4];" \
        : "=r"((r)[0]), "=r"((r)[1]), "=r"((r)[2]), "=r"((r)[3]) : "r"(addr))

#define MMA16816(d, a, b0, b1) \
    asm volatile("mma.sync.aligned.m16n8k16.row.col.f32.bf16.bf16.f32 " \
        "{%0,%1,%2,%3}, {%4,%5,%6,%7}, {%8,%9}, {%0,%1,%2,%3};" \
        : "+f"((d)[0]), "+f"((d)[1]), "+f"((d)[2]), "+f"((d)[3]) \
        : "r"((a)[0]), "r"((a)[1]), "r"((a)[2]), "r"((a)[3]), "r"(b0), "r"(b1))

// d = { lo = bf16(x), hi = bf16(y) }
#define CVT2BF(d, x, y) \
    asm("cvt.rn.bf16x2.f32 %0, %1, %2;" : "=r"(d) : "f"(y), "f"(x))

// ---------------------------------------------------------------------------
// K0: x2, 1/sigma^2, and bf16 hi/lo split of x
// ---------------------------------------------------------------------------
__global__ void k_prep(const float* __restrict__ x,
                       const float* __restrict__ sigma, int D) {
    int b = blockIdx.x;
    const float* xr = x + (size_t)b * D;
    float s = 0.f;
    for (int d = threadIdx.x; d < D; d += blockDim.x) {
        float v = xr[d];
        s += v * v;
        __nv_bfloat16 hi = __float2bfloat16(v);
        float lof = v - __bfloat162float(hi);
        g_xhi[(size_t)b * D + d] = hi;
        g_xlo[(size_t)b * D + d] = __float2bfloat16(lof);
    }
    __shared__ float red[256];
    red[threadIdx.x] = s;
    __syncthreads();
    for (int o = 128; o > 0; o >>= 1) {
        if (threadIdx.x < o) red[threadIdx.x] += red[threadIdx.x + o];
        __syncthreads();
    }
    if (threadIdx.x == 0) {
        g_x2[b] = red[0];
        float sg = sigma[b];
        g_inv[b] = 1.0f / (sg * sg);
    }
}

// ---------------------------------------------------------------------------
// K1: HMMA bf16-split GEMM + fused logits + fused softmax partials.
// CTA tile M=64 x N=128, KC=64, double-buffered, 1 barrier per chunk,
// 2 CTAs per SM.
// ---------------------------------------------------------------------------
#define NT 128
#define KC 64
#define TILE_A_LO 8192
#define TILE_B_HI 16384
#define TILE_B_LO 32768
#define BUF_SZ    49152
#define SOFF_RED  0
#define SOFF_Y2   1024
#define SMEM_PRE  2048
#define SMEM_TOTAL (SMEM_PRE + 1024 + 2 * BUF_SZ)

__global__ void __launch_bounds__(256, 2)
k_gemm(const float* __restrict__ Y, int N, int D) {
    extern __shared__ char smem[];
    uint32_t sb = smem_u32(smem);
    const int t = threadIdx.x, w = t >> 5, lane = t & 31;
    const int n0 = blockIdx.x * NT;

    uint32_t tile0 = (sb + SMEM_PRE + 1023) & ~1023u;
    char* sm_t = smem + (tile0 - sb);
    float* redp = (float*)(smem + SOFF_RED);
    float* y2s  = (float*)(smem + SOFF_Y2);

    const int wm = w & 1;        // M 32-row half
    const int wn = w >> 1;       // N 32-col quarter

    // loaders: Y row r (0..127), 32-float half ch; A row ar, 16-elem grp ap
    const int r  = t >> 1;
    const int ch = (t & 1) * 32;
    int gr = n0 + r; if (gr >= N) gr = N - 1;
    const float* yp = Y + (size_t)gr * D + ch;
    const int ar = t >> 2, ap = t & 3;
    const __nv_bfloat16* xhp = g_xhi + (size_t)ar * D + ap * 16;
    const __nv_bfloat16* xlp = g_xlo + (size_t)ar * D + ap * 16;

    const int rowA = wm * 32 + (lane & 15);
    const int rowB = wn * 32 + (lane & 15);
    const uint32_t kbl = (uint32_t)(lane >> 4) * 16;

    float acc[2][4][4];
#pragma unroll
    for (int i = 0; i < 2; i++)
#pragma unroll
        for (int j = 0; j < 4; j++)
#pragma unroll
            for (int k = 0; k < 4; k++) acc[i][j][k] = 0.f;

    float y2p = 0.f;
    float4 yv[8];
    uint4 ahv[2], alv[2];
    const int NC = D / KC;   // 48

    // prologue: chunk 0 into regs
#pragma unroll
    for (int j = 0; j < 8; j++) yv[j] = *(const float4*)(yp + j * 4);
    ahv[0] = *(const uint4*)(xhp); ahv[1] = *(const uint4*)(xhp + 8);
    alv[0] = *(const uint4*)(xlp); alv[1] = *(const uint4*)(xlp + 8);

#pragma unroll 1
    for (int ci = 0; ci < NC; ci++) {
        int buf = ci & 1;
        // ---- store phase: convert + STS chunk ci into buf
        {
            char* base = sm_t + buf * BUF_SZ;
            char* bh = base + TILE_B_HI;
            char* bl = base + TILE_B_LO;
#pragma unroll
            for (int j = 0; j < 8; j++) {
                float4 v = yv[j];
                y2p = fmaf(v.x, v.x, y2p); y2p = fmaf(v.y, v.y, y2p);
                y2p = fmaf(v.z, v.z, y2p); y2p = fmaf(v.w, v.w, y2p);
                uint32_t h0, h1, l0, l1;
                CVT2BF(h0, v.x, v.y);
                CVT2BF(h1, v.z, v.w);
                float hx = __uint_as_float(h0 << 16);
                float hy = __uint_as_float(h0 & 0xffff0000u);
                float hz = __uint_as_float(h1 << 16);
                float hw = __uint_as_float(h1 & 0xffff0000u);
                CVT2BF(l0, v.x - hx, v.y - hy);
                CVT2BF(l1, v.z - hz, v.w - hw);
                uint32_t bo = SMEM_SWZ((uint32_t)(r * 128 + (ch + j * 4) * 2));
                *(uint2*)(bh + bo) = make_uint2(h0, h1);
                *(uint2*)(bl + bo) = make_uint2(l0, l1);
            }
            char* aH = base;
            char* aL = base + TILE_A_LO;
#pragma unroll
            for (int u = 0; u < 2; u++) {
                uint32_t bo = SMEM_SWZ((uint32_t)(ar * 128 + ap * 32 + u * 16));
                *(uint4*)(aH + bo) = ahv[u];
                *(uint4*)(aL + bo) = alv[u];
            }
        }
        // ---- prefetch chunk ci+1 (latency overlapped by barrier + MMA)
        if (ci + 1 < NC) {
            int k0 = (ci + 1) * KC;
#pragma unroll
            for (int j = 0; j < 8; j++) yv[j] = *(const float4*)(yp + k0 + j * 4);
            ahv[0] = *(const uint4*)(xhp + k0); ahv[1] = *(const uint4*)(xhp + k0 + 8);
            alv[0] = *(const uint4*)(xlp + k0); alv[1] = *(const uint4*)(xlp + k0 + 8);
        }
        __syncthreads();   // single barrier per chunk (double-buffer invariant)

        // ---- MMA phase over buf
        {
            uint32_t base = tile0 + buf * BUF_SZ;
#pragma unroll
            for (int ks = 0; ks < 4; ks++) {
                uint32_t kb = (uint32_t)ks * 32 + kbl;
                uint32_t offA0 = SMEM_SWZ((uint32_t)(rowA * 128) + kb);
                uint32_t offA1 = SMEM_SWZ((uint32_t)((rowA + 16) * 128) + kb);
                uint32_t offB0 = SMEM_SWZ((uint32_t)(rowB * 128) + kb);
                uint32_t offB1 = SMEM_SWZ((uint32_t)((rowB + 16) * 128) + kb);
                uint32_t ah0[4], ah1[4], al0[4], al1[4];
                uint32_t bh0[4], bh1[4], bl0[4], bl1[4];
                LDSM_X4(ah0, base + offA0);
                LDSM_X4(ah1, base + offA1);
                LDSM_X4(al0, base + TILE_A_LO + offA0);
                LDSM_X4(al1, base + TILE_A_LO + offA1);
                LDSM_X4(bh0, base + TILE_B_HI + offB0);
                LDSM_X4(bh1, base + TILE_B_HI + offB1);
                LDSM_X4(bl0, base + TILE_B_LO + offB0);
                LDSM_X4(bl1, base + TILE_B_LO + offB1);
#pragma unroll
                for (int nt = 0; nt < 4; nt++) {
                    uint32_t* BH = (nt < 2) ? bh0 : bh1;
                    uint32_t* BL = (nt < 2) ? bl0 : bl1;
                    int p = nt & 1;
                    uint32_t b0h = BH[p], b1h = BH[2 + p];
                    uint32_t b0l = BL[p], b1l = BL[2 + p];
                    MMA16816(acc[0][nt], ah0, b0h, b1h);
                    MMA16816(acc[1][nt], ah1, b0h, b1h);
                    MMA16816(acc[0][nt], ah0, b0l, b1l);
                    MMA16816(acc[1][nt], ah1, b0l, b1l);
                    MMA16816(acc[0][nt], al0, b0h, b1h);
                    MMA16816(acc[1][nt], al1, b0h, b1h);
                }
            }
        }
    }

    // ---- epilogue: stage dots in SMEM (reuse buf0: 64x128 f32 = 32KB)
    float* lt = (float*)sm_t;
#pragma unroll
    for (int mt = 0; mt < 2; mt++) {
#pragma unroll
        for (int nt = 0; nt < 4; nt++) {
            int mrow = wm * 32 + mt * 16 + (lane >> 2);
            int col  = wn * 32 + nt * 8 + (lane & 3) * 2;
            lt[mrow * 128 + col]           = acc[mt][nt][0];
            lt[mrow * 128 + col + 1]       = acc[mt][nt][1];
            lt[(mrow + 8) * 128 + col]     = acc[mt][nt][2];
            lt[(mrow + 8) * 128 + col + 1] = acc[mt][nt][3];
        }
    }
    redp[t] = y2p;
    __syncthreads();
    if (t < 128) y2s[t] = redp[2 * t] + redp[2 * t + 1];
    __syncthreads();

    const int GB = gridDim.x;
#pragma unroll
    for (int it = 0; it < 8; it++) {
        int b = it * 8 + w;
        int nn = lane * 4;
        int n = n0 + nn;
        float x2b = g_x2[b];
        float iv  = g_inv[b];
        float4 o = make_float4(0.f, 0.f, 0.f, 0.f);
        bool valid = (n < N);              // N % 4 == 0 -> whole float4 valid
        if (valid) {
            float4 dv = *(float4*)(lt + b * 128 + nn);
            o.x = -0.5f * fmaxf(x2b + y2s[nn]     - 2.0f * dv.x, 0.0f) * iv;
            o.y = -0.5f * fmaxf(x2b + y2s[nn + 1] - 2.0f * dv.y, 0.0f) * iv;
            o.z = -0.5f * fmaxf(x2b + y2s[nn + 2] - 2.0f * dv.z, 0.0f) * iv;
            o.w = -0.5f * fmaxf(x2b + y2s[nn + 3] - 2.0f * dv.w, 0.0f) * iv;
            *(float4*)(g_logits + (size_t)b * N + n) = o;
        }
        // fused softmax partials: warp owns row b over 128 cols
        float mx = valid ? fmaxf(fmaxf(o.x, o.y), fmaxf(o.z, o.w)) : -3.4e38f;
#pragma unroll
        for (int q = 16; q > 0; q >>= 1)
            mx = fmaxf(mx, __shfl_xor_sync(0xffffffff, mx, q));
        float se = 0.f;
        if (valid)
            se = expf(o.x - mx) + expf(o.y - mx) + expf(o.z - mx) + expf(o.w - mx);
#pragma unroll
        for (int q = 16; q > 0; q >>= 1)
            se += __shfl_xor_sync(0xffffffff, se, q);
        if (lane == 0) {
            g_pm[(size_t)b * GB + blockIdx.x] = mx;
            g_ps[(size_t)b * GB + blockIdx.x] = se;
        }
    }
}

// ---------------------------------------------------------------------------
// K2: merge per-CTA softmax partials (GB per b)
// ---------------------------------------------------------------------------
__global__ void k_stats_comb(int GB) {
    int b = blockIdx.x, t = threadIdx.x;
    __shared__ float red[256];
    const float* pm = g_pm + (size_t)b * GB;
    const float* ps = g_ps + (size_t)b * GB;
    float m = -3.4e38f;
    for (int i = t; i < GB; i += 256) m = fmaxf(m, pm[i]);
    red[t] = m;
    __syncthreads();
    for (int o = 128; o > 0; o >>= 1) {
        if (t < o) red[t] = fmaxf(red[t], red[t + o]);
        __syncthreads();
    }
    float M = red[0];
    __syncthreads();
    float s = 0.f;
    for (int i = t; i < GB; i += 256) s += ps[i] * expf(pm[i] - M);
    red[t] = s;
    __syncthreads();
    for (int o = 128; o > 0; o >>= 1) {
        if (t < o) red[t] += red[t + o];
        __syncthreads();
    }
    if (t == 0) { g_m[b] = M; g_is[b] = 1.0f / red[0]; }
}

// ---------------------------------------------------------------------------
// K3: zero out, then sparse weighted gather with slice parallelism.
// ---------------------------------------------------------------------------
__global__ void k_zero(float* out, int n) {
    int i = blockIdx.x * blockDim.x + threadIdx.x;
    if (i < n) out[i] = 0.f;
}

#define OCHUNK 1024
#define DREG (DFIX / 256)

__global__ void __launch_bounds__(256)
k_out(const float* __restrict__ Y, float* __restrict__ out, int N, int D) {
    int b = blockIdx.x, s = blockIdx.y, t = threadIdx.x;
    int L = (N + 15) / 16;
    int st = s * L, en = min(N, st + L);
    __shared__ int lidx[OCHUNK];
    __shared__ float lw[OCHUNK];
    __shared__ int cnt;

    float racc[DREG];
#pragma unroll
    for (int i = 0; i < DREG; i++) racc[i] = 0.f;
    if (t == 0) cnt = 0;

    float M  = g_m[b];
    float IS = g_is[b];
    const float* row = g_logits + (size_t)b * N;
    int tot = 0;

    for (int c0 = st; c0 < en; c0 += OCHUNK) {
        __syncthreads();
#pragma unroll
        for (int j = 0; j < OCHUNK / 256; j++) {
            int n = c0 + j * 256 + t;
            if (n < en) {
                float wv = expf(row[n] - M) * IS;
                if (wv > 1e-12f) {
                    int p = atomicAdd(&cnt, 1);
                    lidx[p] = n;
                    lw[p] = wv;
                }
            }
        }
        __syncthreads();
        int c = cnt;
        tot += c;
        for (int e = 0; e < c; e++) {
            int n = lidx[e];
            float wv = lw[e];
            const float* yr = Y + (size_t)n * D + t;
#pragma unroll
            for (int i = 0; i < DREG; i++)
                racc[i] = fmaf(wv, yr[i * 256], racc[i]);
        }
        __syncthreads();
        if (t == 0) cnt = 0;
    }
    if (tot > 0) {
#pragma unroll
        for (int i = 0; i < DREG; i++)
            atomicAdd(&out[(size_t)b * D + t + i * 256], racc[i]);
    }
}

// ---------------------------------------------------------------------------
extern "C" void kernel_launch(void* const* d_in, const int* in_sizes, int n_in,
                              void* d_out, int out_size) {
    const float* x     = (const float*)d_in[0];
    const float* sigma = (const float*)d_in[1];
    const float* Y     = (const float*)d_in[2];
    float* out = (float*)d_out;

    int B = in_sizes[1];             // 64
    int D = in_sizes[0] / B;         // 3072
    int N = in_sizes[2] / D;         // 50000
    int GB = (N + NT - 1) / NT;      // 391

    cudaFuncSetAttribute(k_gemm, cudaFuncAttributeMaxDynamicSharedMemorySize, SMEM_TOTAL);

    k_prep<<<B, 256>>>(x, sigma, D);
    k_gemm<<<GB, 256, SMEM_TOTAL>>>(Y, N, D);
    k_stats_comb<<<B, 256>>>(GB);
    k_zero<<<(B * D + 255) / 256, 256>>>(out, B * D);
    dim3 go(B, 16);
    k_out<<<go, 256>>>(Y, out, N, D);
}

// round 5
// speedup vs baseline: 3.2136x; 1.1683x over previous
#include <cuda_runtime.h>
#include <cuda_bf16.h>
#include <math.h>
#include <stdint.h>

// Fixed problem shape: B=64, D=3072, N=50000.
#define BFIX 64
#define DFIX 3072

// ---------------- scratch (__device__ globals: allocation-free) -------------
__device__ float g_logits[(size_t)BFIX * 50048];
__device__ float g_x2[BFIX];
__device__ float g_inv[BFIX];
__device__ float g_m[BFIX];
__device__ float g_is[BFIX];
__device__ __nv_bfloat16 g_xhi[BFIX * DFIX];
__device__ __nv_bfloat16 g_xlo[BFIX * DFIX];
__device__ float g_pm[BFIX * 512];
__device__ float g_ps[BFIX * 512];

// ---------------- helpers ----------------------------------------------------
__device__ __forceinline__ uint32_t smem_u32(const void* p) {
    uint32_t a;
    asm("{ .reg .u64 t; cvta.to.shared.u64 t, %1; cvt.u32.u64 %0, t; }"
        : "=r"(a) : "l"(p));
    return a;
}
#define SMEM_SWZ(o) ((o) ^ (((o) >> 3) & 0x70))

#define LDSM_X4(r, addr) \
    asm volatile("ldmatrix.sync.aligned.m8n8.x4.shared.b16 {%0,%1,%2,%3}, [%4];" \
        : "=r"((r)[0]), "=r"((r)[1]), "=r"((r)[2]), "=r"((r)[3]) : "r"(addr))

#define MMA16816(d, a, b0, b1) \
    asm volatile("mma.sync.aligned.m16n8k16.row.col.f32.bf16.bf16.f32 " \
        "{%0,%1,%2,%3}, {%4,%5,%6,%7}, {%8,%9}, {%0,%1,%2,%3};" \
        : "+f"((d)[0]), "+f"((d)[1]), "+f"((d)[2]), "+f"((d)[3]) \
        : "r"((a)[0]), "r"((a)[1]), "r"((a)[2]), "r"((a)[3]), "r"(b0), "r"(b1))

// d = { lo = bf16(x), hi = bf16(y) }
#define CVT2BF(d, x, y) \
    asm("cvt.rn.bf16x2.f32 %0, %1, %2;" : "=r"(d) : "f"(y), "f"(x))

#define MBARRIER_INIT(addr, cnt) \
    asm volatile("mbarrier.init.shared.b64 [%0], %1;" :: "r"((uint32_t)(addr)), "r"((uint32_t)(cnt)) : "memory")
#define MBARRIER_ARRIVE(addr) \
    asm volatile("mbarrier.arrive.shared.b64 _, [%0];" :: "r"((uint32_t)(addr)) : "memory")
#define MBARRIER_WAIT_PARITY(mbar_smem_addr, phase_parity) do { \
    uint32_t _mbar = (uint32_t)(mbar_smem_addr); \
    uint32_t _parity = (uint32_t)(phase_parity); \
    uint32_t _done; \
    asm volatile("{\n\t.reg .pred p;\n\t" \
        "mbarrier.try_wait.parity.shared.b64 p, [%1], %2;\n\t" \
        "selp.b32 %0, 1, 0, p;\n\t}" : "=r"(_done) : "r"(_mbar), "r"(_parity) : "memory"); \
    if (!_done) { \
        asm volatile("{\n\t.reg .pred P1;\n\t" \
            "WAIT_LOOP_%=:\n\t" \
            "mbarrier.try_wait.parity.shared.b64 P1, [%0], %1;\n\t" \
            "@P1 bra.uni WAIT_DONE_%=;\n\t" \
            "bra.uni WAIT_LOOP_%=;\n\t" \
            "WAIT_DONE_%=:\n\t}" :: "r"(_mbar), "r"(_parity) : "memory"); \
    } \
} while (0)

// ---------------------------------------------------------------------------
// K0: x2, 1/sigma^2, and bf16 hi/lo split of x
// ---------------------------------------------------------------------------
__global__ void k_prep(const float* __restrict__ x,
                       const float* __restrict__ sigma, int D) {
    int b = blockIdx.x;
    const float* xr = x + (size_t)b * D;
    float s = 0.f;
    for (int d = threadIdx.x; d < D; d += blockDim.x) {
        float v = xr[d];
        s += v * v;
        __nv_bfloat16 hi = __float2bfloat16(v);
        float lof = v - __bfloat162float(hi);
        g_xhi[(size_t)b * D + d] = hi;
        g_xlo[(size_t)b * D + d] = __float2bfloat16(lof);
    }
    __shared__ float red[256];
    red[threadIdx.x] = s;
    __syncthreads();
    for (int o = 128; o > 0; o >>= 1) {
        if (threadIdx.x < o) red[threadIdx.x] += red[threadIdx.x + o];
        __syncthreads();
    }
    if (threadIdx.x == 0) {
        g_x2[b] = red[0];
        float sg = sigma[b];
        g_inv[b] = 1.0f / (sg * sg);
    }
}

// ---------------------------------------------------------------------------
// K1: warp-specialized HMMA bf16-split GEMM + fused logits/softmax partials.
// 512 threads: warps 0-7 produce (LDG->convert->STS), warps 8-15 consume
// (LDSM->MMA). 2-stage double buffer, mbarrier full/empty handoff.
// ---------------------------------------------------------------------------
#define NT 128
#define KC 64
#define TILE_A_LO 8192
#define TILE_B_HI 16384
#define TILE_B_LO 32768
#define BUF_SZ    49152
#define SOFF_RED  0
#define SOFF_Y2   1024
#define SOFF_BAR  1536          // full0, empty0, full1, empty1 (8B each)
#define SMEM_PRE  2048
#define SMEM_TOTAL (SMEM_PRE + 1024 + 2 * BUF_SZ)

__global__ void __launch_bounds__(512, 1)
k_gemm(const float* __restrict__ Y, int N, int D) {
    extern __shared__ char smem[];
    uint32_t sb = smem_u32(smem);
    const int t = threadIdx.x, w = t >> 5, lane = t & 31;
    const int n0 = blockIdx.x * NT;
    const int NC = D / KC;   // 48

    uint32_t tile0 = (sb + SMEM_PRE + 1023) & ~1023u;
    char* sm_t = smem + (tile0 - sb);
    float* redp = (float*)(smem + SOFF_RED);
    float* y2s  = (float*)(smem + SOFF_Y2);
    uint32_t bar_full[2]  = { sb + SOFF_BAR,      sb + SOFF_BAR + 16 };
    uint32_t bar_empty[2] = { sb + SOFF_BAR + 8,  sb + SOFF_BAR + 24 };

    if (t == 0) {
        MBARRIER_INIT(bar_full[0], 256);
        MBARRIER_INIT(bar_empty[0], 256);
        MBARRIER_INIT(bar_full[1], 256);
        MBARRIER_INIT(bar_empty[1], 256);
    }
    __syncthreads();

    float y2p = 0.f;
    float acc[2][4][4];
#pragma unroll
    for (int i = 0; i < 2; i++)
#pragma unroll
        for (int j = 0; j < 4; j++)
#pragma unroll
            for (int k = 0; k < 4; k++) acc[i][j][k] = 0.f;

    if (t < 256) {
        // ================= PRODUCER (warps 0-7) =================
        const int r  = t >> 1;
        const int ch = (t & 1) * 32;
        int gr = n0 + r; if (gr >= N) gr = N - 1;
        const float* yp = Y + (size_t)gr * D + ch;
        const int ar = t >> 2, ap = t & 3;
        const __nv_bfloat16* xhp = g_xhi + (size_t)ar * D + ap * 16;
        const __nv_bfloat16* xlp = g_xlo + (size_t)ar * D + ap * 16;

        float4 yv[8];
        uint4 ahv[2], alv[2];
#pragma unroll
        for (int j = 0; j < 8; j++) yv[j] = *(const float4*)(yp + j * 4);
        ahv[0] = *(const uint4*)(xhp); ahv[1] = *(const uint4*)(xhp + 8);
        alv[0] = *(const uint4*)(xlp); alv[1] = *(const uint4*)(xlp + 8);

        int ep[2] = { 1, 1 };
#pragma unroll 1
        for (int ci = 0; ci < NC; ci++) {
            int buf = ci & 1;
            MBARRIER_WAIT_PARITY(bar_empty[buf], ep[buf]);
            ep[buf] ^= 1;
            {
                char* base = sm_t + buf * BUF_SZ;
                char* bh = base + TILE_B_HI;
                char* bl = base + TILE_B_LO;
#pragma unroll
                for (int j = 0; j < 8; j++) {
                    float4 v = yv[j];
                    y2p = fmaf(v.x, v.x, y2p); y2p = fmaf(v.y, v.y, y2p);
                    y2p = fmaf(v.z, v.z, y2p); y2p = fmaf(v.w, v.w, y2p);
                    uint32_t h0, h1, l0, l1;
                    CVT2BF(h0, v.x, v.y);
                    CVT2BF(h1, v.z, v.w);
                    float hx = __uint_as_float(h0 << 16);
                    float hy = __uint_as_float(h0 & 0xffff0000u);
                    float hz = __uint_as_float(h1 << 16);
                    float hw = __uint_as_float(h1 & 0xffff0000u);
                    CVT2BF(l0, v.x - hx, v.y - hy);
                    CVT2BF(l1, v.z - hz, v.w - hw);
                    uint32_t bo = SMEM_SWZ((uint32_t)(r * 128 + (ch + j * 4) * 2));
                    *(uint2*)(bh + bo) = make_uint2(h0, h1);
                    *(uint2*)(bl + bo) = make_uint2(l0, l1);
                }
                char* aH = base;
                char* aL = base + TILE_A_LO;
#pragma unroll
                for (int u = 0; u < 2; u++) {
                    uint32_t bo = SMEM_SWZ((uint32_t)(ar * 128 + ap * 32 + u * 16));
                    *(uint4*)(aH + bo) = ahv[u];
                    *(uint4*)(aL + bo) = alv[u];
                }
            }
            MBARRIER_ARRIVE(bar_full[buf]);
            if (ci + 1 < NC) {
                int k0 = (ci + 1) * KC;
#pragma unroll
                for (int j = 0; j < 8; j++) yv[j] = *(const float4*)(yp + k0 + j * 4);
                ahv[0] = *(const uint4*)(xhp + k0); ahv[1] = *(const uint4*)(xhp + k0 + 8);
                alv[0] = *(const uint4*)(xlp + k0); alv[1] = *(const uint4*)(xlp + k0 + 8);
            }
        }
    } else {
        // ================= CONSUMER (warps 8-15) =================
        const int cw = w - 8;
        const int wm = cw & 1;
        const int wn = cw >> 1;
        const int rowA = wm * 32 + (lane & 15);
        const int rowB = wn * 32 + (lane & 15);
        const uint32_t kbl = (uint32_t)(lane >> 4) * 16;

        int fp[2] = { 0, 0 };
#pragma unroll 1
        for (int ci = 0; ci < NC; ci++) {
            int buf = ci & 1;
            MBARRIER_WAIT_PARITY(bar_full[buf], fp[buf]);
            fp[buf] ^= 1;
            uint32_t base = tile0 + buf * BUF_SZ;
#pragma unroll
            for (int ks = 0; ks < 4; ks++) {
                uint32_t kb = (uint32_t)ks * 32 + kbl;
                uint32_t offA0 = SMEM_SWZ((uint32_t)(rowA * 128) + kb);
                uint32_t offA1 = SMEM_SWZ((uint32_t)((rowA + 16) * 128) + kb);
                uint32_t offB0 = SMEM_SWZ((uint32_t)(rowB * 128) + kb);
                uint32_t offB1 = SMEM_SWZ((uint32_t)((rowB + 16) * 128) + kb);
                uint32_t ah0[4], ah1[4], al0[4], al1[4];
                uint32_t bh0[4], bh1[4], bl0[4], bl1[4];
                LDSM_X4(ah0, base + offA0);
                LDSM_X4(ah1, base + offA1);
                LDSM_X4(al0, base + TILE_A_LO + offA0);
                LDSM_X4(al1, base + TILE_A_LO + offA1);
                LDSM_X4(bh0, base + TILE_B_HI + offB0);
                LDSM_X4(bh1, base + TILE_B_HI + offB1);
                LDSM_X4(bl0, base + TILE_B_LO + offB0);
                LDSM_X4(bl1, base + TILE_B_LO + offB1);
#pragma unroll
                for (int nt = 0; nt < 4; nt++) {
                    uint32_t* BH = (nt < 2) ? bh0 : bh1;
                    uint32_t* BL = (nt < 2) ? bl0 : bl1;
                    int p = nt & 1;
                    uint32_t b0h = BH[p], b1h = BH[2 + p];
                    uint32_t b0l = BL[p], b1l = BL[2 + p];
                    MMA16816(acc[0][nt], ah0, b0h, b1h);
                    MMA16816(acc[1][nt], ah1, b0h, b1h);
                    MMA16816(acc[0][nt], ah0, b0l, b1l);
                    MMA16816(acc[1][nt], ah1, b0l, b1l);
                    MMA16816(acc[0][nt], al0, b0h, b1h);
                    MMA16816(acc[1][nt], al1, b0h, b1h);
                }
            }
            MBARRIER_ARRIVE(bar_empty[buf]);
        }
    }

    // ================= EPILOGUE (all 512 threads) =================
    if (t < 256) redp[t] = y2p;
    __syncthreads();

    float* lt = (float*)sm_t;   // reuse stage-0 buffer: 64x128 f32 = 32KB
    if (w >= 8) {
        const int cw = w - 8;
        const int wm = cw & 1;
        const int wn = cw >> 1;
#pragma unroll
        for (int mt = 0; mt < 2; mt++) {
#pragma unroll
            for (int nt = 0; nt < 4; nt++) {
                int mrow = wm * 32 + mt * 16 + (lane >> 2);
                int col  = wn * 32 + nt * 8 + (lane & 3) * 2;
                lt[mrow * 128 + col]           = acc[mt][nt][0];
                lt[mrow * 128 + col + 1]       = acc[mt][nt][1];
                lt[(mrow + 8) * 128 + col]     = acc[mt][nt][2];
                lt[(mrow + 8) * 128 + col + 1] = acc[mt][nt][3];
            }
        }
    }
    if (t < 128) y2s[t] = redp[2 * t] + redp[2 * t + 1];
    __syncthreads();

    const int GB = gridDim.x;
#pragma unroll
    for (int it = 0; it < 4; it++) {
        int b = it * 16 + w;
        int nn = lane * 4;
        int n = n0 + nn;
        float x2b = g_x2[b];
        float iv  = g_inv[b];
        float4 o = make_float4(0.f, 0.f, 0.f, 0.f);
        bool valid = (n < N);              // N % 4 == 0 -> whole float4 valid
        if (valid) {
            float4 dv = *(float4*)(lt + b * 128 + nn);
            o.x = -0.5f * fmaxf(x2b + y2s[nn]     - 2.0f * dv.x, 0.0f) * iv;
            o.y = -0.5f * fmaxf(x2b + y2s[nn + 1] - 2.0f * dv.y, 0.0f) * iv;
            o.z = -0.5f * fmaxf(x2b + y2s[nn + 2] - 2.0f * dv.z, 0.0f) * iv;
            o.w = -0.5f * fmaxf(x2b + y2s[nn + 3] - 2.0f * dv.w, 0.0f) * iv;
            *(float4*)(g_logits + (size_t)b * N + n) = o;
        }
        float mx = valid ? fmaxf(fmaxf(o.x, o.y), fmaxf(o.z, o.w)) : -3.4e38f;
#pragma unroll
        for (int q = 16; q > 0; q >>= 1)
            mx = fmaxf(mx, __shfl_xor_sync(0xffffffff, mx, q));
        float se = 0.f;
        if (valid)
            se = expf(o.x - mx) + expf(o.y - mx) + expf(o.z - mx) + expf(o.w - mx);
#pragma unroll
        for (int q = 16; q > 0; q >>= 1)
            se += __shfl_xor_sync(0xffffffff, se, q);
        if (lane == 0) {
            g_pm[(size_t)b * GB + blockIdx.x] = mx;
            g_ps[(size_t)b * GB + blockIdx.x] = se;
        }
    }
}

// ---------------------------------------------------------------------------
// K2: merge per-CTA softmax partials (GB per b)
// ---------------------------------------------------------------------------
__global__ void k_stats_comb(int GB) {
    int b = blockIdx.x, t = threadIdx.x;
    __shared__ float red[256];
    const float* pm = g_pm + (size_t)b * GB;
    const float* ps = g_ps + (size_t)b * GB;
    float m = -3.4e38f;
    for (int i = t; i < GB; i += 256) m = fmaxf(m, pm[i]);
    red[t] = m;
    __syncthreads();
    for (int o = 128; o > 0; o >>= 1) {
        if (t < o) red[t] = fmaxf(red[t], red[t + o]);
        __syncthreads();
    }
    float M = red[0];
    __syncthreads();
    float s = 0.f;
    for (int i = t; i < GB; i += 256) s += ps[i] * expf(pm[i] - M);
    red[t] = s;
    __syncthreads();
    for (int o = 128; o > 0; o >>= 1) {
        if (t < o) red[t] += red[t + o];
        __syncthreads();
    }
    if (t == 0) { g_m[b] = M; g_is[b] = 1.0f / red[0]; }
}

// ---------------------------------------------------------------------------
// K3: zero out, then sparse weighted gather with slice parallelism.
// ---------------------------------------------------------------------------
__global__ void k_zero(float* out, int n) {
    int i = blockIdx.x * blockDim.x + threadIdx.x;
    if (i < n) out[i] = 0.f;
}

#define OCHUNK 1024
#define DREG (DFIX / 256)

__global__ void __launch_bounds__(256)
k_out(const float* __restrict__ Y, float* __restrict__ out, int N, int D) {
    int b = blockIdx.x, s = blockIdx.y, t = threadIdx.x;
    int L = (N + 15) / 16;
    int st = s * L, en = min(N, st + L);
    __shared__ int lidx[OCHUNK];
    __shared__ float lw[OCHUNK];
    __shared__ int cnt;

    float racc[DREG];
#pragma unroll
    for (int i = 0; i < DREG; i++) racc[i] = 0.f;
    if (t == 0) cnt = 0;

    float M  = g_m[b];
    float IS = g_is[b];
    const float* row = g_logits + (size_t)b * N;
    int tot = 0;

    for (int c0 = st; c0 < en; c0 += OCHUNK) {
        __syncthreads();
#pragma unroll
        for (int j = 0; j < OCHUNK / 256; j++) {
            int n = c0 + j * 256 + t;
            if (n < en) {
                float wv = expf(row[n] - M) * IS;
                if (wv > 1e-12f) {
                    int p = atomicAdd(&cnt, 1);
                    lidx[p] = n;
                    lw[p] = wv;
                }
            }
        }
        __syncthreads();
        int c = cnt;
        tot += c;
        for (int e = 0; e < c; e++) {
            int n = lidx[e];
            float wv = lw[e];
            const float* yr = Y + (size_t)n * D + t;
#pragma unroll
            for (int i = 0; i < DREG; i++)
                racc[i] = fmaf(wv, yr[i * 256], racc[i]);
        }
        __syncthreads();
        if (t == 0) cnt = 0;
    }
    if (tot > 0) {
#pragma unroll
        for (int i = 0; i < DREG; i++)
            atomicAdd(&out[(size_t)b * D + t + i * 256], racc[i]);
    }
}

// ---------------------------------------------------------------------------
extern "C" void kernel_launch(void* const* d_in, const int* in_sizes, int n_in,
                              void* d_out, int out_size) {
    const float* x     = (const float*)d_in[0];
    const float* sigma = (const float*)d_in[1];
    const float* Y     = (const float*)d_in[2];
    float* out = (float*)d_out;

    int B = in_sizes[1];             // 64
    int D = in_sizes[0] / B;         // 3072
    int N = in_sizes[2] / D;         // 50000
    int GB = (N + NT - 1) / NT;      // 391

    cudaFuncSetAttribute(k_gemm, cudaFuncAttributeMaxDynamicSharedMemorySize, SMEM_TOTAL);

    k_prep<<<B, 256>>>(x, sigma, D);
    k_gemm<<<GB, 512, SMEM_TOTAL>>>(Y, N, D);
    k_stats_comb<<<B, 256>>>(GB);
    k_zero<<<(B * D + 255) / 256, 256>>>(out, B * D);
    dim3 go(B, 16);
    k_out<<<go, 256>>>(Y, out, N, D);
}